// round 8
// baseline (speedup 1.0000x reference)
#include <cuda_runtime.h>
#include <math.h>

#define SELF_DIM  36
#define OTHER_DIM 28
#define OTHER_NUM 19
#define OBS_DIM   568        // 36 + 28*19
#define HID       64
#define NW        8          // warps per block
#define RPW       4          // rows per warp per group
#define ROWS_PER_GROUP (NW * RPW)

// Scratch (allocation-free): fused matrix M'[64][64], bias c[64], attention weights w[28]
__device__ float g_M[64 * 64];
__device__ float g_c[64];
__device__ float g_w[OTHER_DIM];

// ---------------------------------------------------------------------------
// Precompute:  M'[k][h] = (We @ Wo[:64])[k][h] + (k<36 ? ((Ws[:36]+Ws[36:]) @ Wo[64:])[k][h] : 0)
//              c[h]     = bo[h] + be @ Wo[:64] + bs @ Wo[64:]
//              w[d]     = Wa[36+d]   (self part + ba are softmax-invariant -> dropped)
// ---------------------------------------------------------------------------
__global__ void precompute_kernel(const float* __restrict__ Wa,
                                  const float* __restrict__ We,
                                  const float* __restrict__ be,
                                  const float* __restrict__ Ws,
                                  const float* __restrict__ bs,
                                  const float* __restrict__ Wo,
                                  const float* __restrict__ bo) {
    int k = blockIdx.x;   // 0..63 (input dim of We)
    int h = threadIdx.x;  // 0..63 (output dim)
    float acc = 0.f;
    #pragma unroll 8
    for (int j = 0; j < 64; j++)
        acc += We[k * HID + j] * Wo[j * HID + h];
    if (k < SELF_DIM) {
        #pragma unroll 8
        for (int j = 0; j < 64; j++)
            acc += (Ws[k * HID + j] + Ws[(k + SELF_DIM) * HID + j]) * Wo[(64 + j) * HID + h];
    }
    g_M[k * HID + h] = acc;

    if (k == 0) {
        float cc = bo[h];
        #pragma unroll 8
        for (int j = 0; j < 64; j++)
            cc += be[j] * Wo[j * HID + h] + bs[j] * Wo[(64 + j) * HID + h];
        g_c[h] = cc;
        if (h < OTHER_DIM) g_w[h] = Wa[SELF_DIM + h];
    }
}

// ---------------------------------------------------------------------------
// Main kernel: per row
//   logits_i = others_i . w           (19 x 28 dots, lane i)
//   att      = softmax(logits)        (warp shuffle reduce)
//   pooled   = [self(36), sum_i att_i * others_i (28)]
//   out      = pooled @ M' + c        (4-row register-blocked warp GEMM)
// ---------------------------------------------------------------------------
__global__ void __launch_bounds__(256)
gat_kernel(const float* __restrict__ x, float* __restrict__ out,
           int nrows, int ngroups) {
    __shared__ float Msh[64 * 64];            // 16 KB
    __shared__ float csh[64];
    __shared__ float wsh[OTHER_DIM];
    __shared__ float sx[NW][OBS_DIM];         // 8 * 2272 B staging
    __shared__ float att_sh[NW][20];
    __shared__ float pv[NW][RPW][64];         // pooled64 vectors, 8 KB

    const int tid  = threadIdx.x;
    const int warp = tid >> 5;
    const int lane = tid & 31;

    // Load fused weights into shared once per block
    for (int i = tid; i < 64 * 64; i += 256) Msh[i] = g_M[i];
    if (tid < 64)            csh[tid]      = g_c[tid];
    if (tid >= 64 && tid < 64 + OTHER_DIM) wsh[tid - 64] = g_w[tid - 64];
    __syncthreads();

    for (int g = blockIdx.x; g < ngroups; g += gridDim.x) {
        const int rbase = g * ROWS_PER_GROUP + warp * RPW;

        // ---- steps 1-5 for 4 rows, one at a time (warp-private) ----
        #pragma unroll 1
        for (int j = 0; j < RPW; j++) {
            const int row = rbase + j;
            if (row >= nrows) break;

            // stage row into shared (coalesced float4)
            const float4* xr = reinterpret_cast<const float4*>(x + (size_t)row * OBS_DIM);
            float4* s4 = reinterpret_cast<float4*>(sx[warp]);
            for (int i = lane; i < OBS_DIM / 4; i += 32) s4[i] = xr[i];
            __syncwarp();

            // logits (lane i handles slot i)
            float logit = -1e30f;
            if (lane < OTHER_NUM) {
                const float* o = &sx[warp][SELF_DIM + lane * OTHER_DIM];
                float acc = 0.f;
                #pragma unroll
                for (int d = 0; d < OTHER_DIM; d += 4) {
                    float4 ov = *reinterpret_cast<const float4*>(o + d);
                    float4 wv = *reinterpret_cast<const float4*>(wsh + d);
                    acc += ov.x * wv.x + ov.y * wv.y + ov.z * wv.z + ov.w * wv.w;
                }
                logit = acc;
            }

            // warp softmax over lanes 0..18
            float mx = logit;
            #pragma unroll
            for (int off = 16; off > 0; off >>= 1)
                mx = fmaxf(mx, __shfl_xor_sync(0xffffffffu, mx, off));
            float e = (lane < OTHER_NUM) ? __expf(logit - mx) : 0.f;
            float sm = e;
            #pragma unroll
            for (int off = 16; off > 0; off >>= 1)
                sm += __shfl_xor_sync(0xffffffffu, sm, off);
            if (lane < OTHER_NUM) att_sh[warp][lane] = e / sm;
            __syncwarp();

            // pooled_other (lane d handles feature d) + copy self into pv
            if (lane < OTHER_DIM) {
                float p = 0.f;
                #pragma unroll
                for (int i = 0; i < OTHER_NUM; i++)
                    p += att_sh[warp][i] * sx[warp][SELF_DIM + i * OTHER_DIM + lane];
                pv[warp][j][SELF_DIM + lane] = p;
            }
            pv[warp][j][lane] = sx[warp][lane];                       // self[0..31]
            if (lane < SELF_DIM - 32)
                pv[warp][j][32 + lane] = sx[warp][32 + lane];         // self[32..35]
            __syncwarp();
        }

        // ---- step 6: 4-row register-blocked GEMM: out = pv @ M' + c ----
        float acc0[RPW], acc1[RPW];
        #pragma unroll
        for (int j = 0; j < RPW; j++) { acc0[j] = csh[lane]; acc1[j] = csh[lane + 32]; }

        #pragma unroll 4
        for (int k = 0; k < 64; k += 4) {
            float4 q0 = *reinterpret_cast<const float4*>(&pv[warp][0][k]);
            float4 q1 = *reinterpret_cast<const float4*>(&pv[warp][1][k]);
            float4 q2 = *reinterpret_cast<const float4*>(&pv[warp][2][k]);
            float4 q3 = *reinterpret_cast<const float4*>(&pv[warp][3][k]);
            float P[4][4];
            P[0][0] = q0.x; P[0][1] = q0.y; P[0][2] = q0.z; P[0][3] = q0.w;
            P[1][0] = q1.x; P[1][1] = q1.y; P[1][2] = q1.z; P[1][3] = q1.w;
            P[2][0] = q2.x; P[2][1] = q2.y; P[2][2] = q2.z; P[2][3] = q2.w;
            P[3][0] = q3.x; P[3][1] = q3.y; P[3][2] = q3.z; P[3][3] = q3.w;
            #pragma unroll
            for (int kk = 0; kk < 4; kk++) {
                float m0 = Msh[(k + kk) * 64 + lane];
                float m1 = Msh[(k + kk) * 64 + lane + 32];
                #pragma unroll
                for (int j = 0; j < RPW; j++) {
                    acc0[j] += P[j][kk] * m0;
                    acc1[j] += P[j][kk] * m1;
                }
            }
        }

        #pragma unroll
        for (int j = 0; j < RPW; j++) {
            const int row = rbase + j;
            if (row < nrows) {
                out[(size_t)row * HID + lane]      = acc0[j];
                out[(size_t)row * HID + lane + 32] = acc1[j];
            }
        }
    }
}

// ---------------------------------------------------------------------------
extern "C" void kernel_launch(void* const* d_in, const int* in_sizes, int n_in,
                              void* d_out, int out_size) {
    const float* x  = (const float*)d_in[0];
    const float* Wa = (const float*)d_in[1];
    // d_in[2] = ba : softmax-invariant, unused
    const float* We = (const float*)d_in[3];
    const float* be = (const float*)d_in[4];
    const float* Ws = (const float*)d_in[5];
    const float* bs = (const float*)d_in[6];
    const float* Wo = (const float*)d_in[7];
    const float* bo = (const float*)d_in[8];
    float* out = (float*)d_out;

    const int nrows = in_sizes[0] / OBS_DIM;

    precompute_kernel<<<64, 64>>>(Wa, We, be, Ws, bs, Wo, bo);

    const int ngroups = (nrows + ROWS_PER_GROUP - 1) / ROWS_PER_GROUP;
    int grid = ngroups < 888 ? ngroups : 888;   // persistent grid-stride, M' loaded once per block
    gat_kernel<<<grid, 256>>>(x, out, nrows, ngroups);
}

// round 9
// speedup vs baseline: 1.1835x; 1.1835x over previous
#include <cuda_runtime.h>
#include <math.h>

#define SELF_DIM  36
#define OTHER_DIM 28
#define OTHER_NUM 19
#define OBS_DIM   568        // 36 + 28*19
#define HID       64
#define NW        6          // warps per block
#define RPW       8          // rows per warp per GEMM group
#define RPG       (NW * RPW) // 48 rows per group

// Scratch (allocation-free). Aligned so we can read as float2/float4.
__device__ __align__(16) float g_M[64 * 64];
__device__ __align__(16) float g_c[64];
__device__ __align__(16) float g_w[OTHER_DIM];

// ---------------------------------------------------------------------------
// Fused-weight precompute:
//   M'[k][h] = (We @ Wo[:64])[k][h] + (k<36 ? ((Ws[:36]+Ws[36:]) @ Wo[64:])[k][h] : 0)
//   c[h]     = bo[h] + be @ Wo[:64] + bs @ Wo[64:]
//   w[d]     = Wa[36+d]    (self part of logits + ba are softmax-invariant)
// ---------------------------------------------------------------------------
__global__ void precompute_kernel(const float* __restrict__ Wa,
                                  const float* __restrict__ We,
                                  const float* __restrict__ be,
                                  const float* __restrict__ Ws,
                                  const float* __restrict__ bs,
                                  const float* __restrict__ Wo,
                                  const float* __restrict__ bo) {
    int k = blockIdx.x;   // 0..63
    int h = threadIdx.x;  // 0..63
    float acc = 0.f;
    #pragma unroll 8
    for (int j = 0; j < 64; j++)
        acc += We[k * HID + j] * Wo[j * HID + h];
    if (k < SELF_DIM) {
        #pragma unroll 8
        for (int j = 0; j < 64; j++)
            acc += (Ws[k * HID + j] + Ws[(k + SELF_DIM) * HID + j]) * Wo[(64 + j) * HID + h];
    }
    g_M[k * HID + h] = acc;

    if (k == 0) {
        float cc = bo[h];
        #pragma unroll 8
        for (int j = 0; j < 64; j++)
            cc += be[j] * Wo[j * HID + h] + bs[j] * Wo[(64 + j) * HID + h];
        g_c[h] = cc;
        if (h < OTHER_DIM) g_w[h] = Wa[SELF_DIM + h];
    }
}

// ---------------------------------------------------------------------------
// Packed fp32x2 helpers (Blackwell SIMD fp32; only reachable via PTX).
// ---------------------------------------------------------------------------
typedef unsigned long long u64;

__device__ __forceinline__ u64 pk2(float x, float y) {
    u64 u;
    asm("mov.b64 %0, {%1, %2};" : "=l"(u) : "f"(x), "f"(y));
    return u;
}
__device__ __forceinline__ float2 upk2(u64 u) {
    float2 f;
    asm("mov.b64 {%0, %1}, %2;" : "=f"(f.x), "=f"(f.y) : "l"(u));
    return f;
}
__device__ __forceinline__ u64 ffma2(u64 a, u64 b, u64 c) {
    u64 d;
    asm("fma.rn.f32x2 %0, %1, %2, %3;" : "=l"(d) : "l"(a), "l"(b), "l"(c));
    return d;
}

// ---------------------------------------------------------------------------
// Main kernel. Per row (one warp, 8 rows batched):
//   logits_i = others_i . w     (lane i, conflict-aware float4 smem reads)
//   att      = softmax          (warp shuffles)
//   pooled   = [self(36), sum_i att_i * others_i]   (lane d, conflict-free)
//   out      = pooled @ M' + c  (8-row register-blocked, f32x2-packed GEMM)
// Row staging is software-pipelined: next row's gmem loads issue while the
// current row computes, so DRAM latency is hidden inside the warp.
// ---------------------------------------------------------------------------
__global__ void __launch_bounds__(NW * 32)
gat_kernel(const float* __restrict__ x, float* __restrict__ out,
           int nrows, int ngroups) {
    __shared__ float4 sx4[NW][OBS_DIM / 4];          // 6 * 2272 B row staging
    __shared__ __align__(16) float Msh[64 * 64];     // 16 KB fused matrix
    __shared__ __align__(16) float pv[NW][RPW][64];  // pooled vectors, 12 KB
    __shared__ __align__(8)  float csh[64];
    __shared__ __align__(16) float wsh[OTHER_DIM];

    const int tid  = threadIdx.x;
    const int warp = tid >> 5;
    const int lane = tid & 31;

    for (int i = tid; i < 64 * 64; i += NW * 32) Msh[i] = g_M[i];
    if (tid < 64)                          csh[tid]      = g_c[tid];
    if (tid >= 64 && tid < 64 + OTHER_DIM) wsh[tid - 64] = g_w[tid - 64];
    __syncthreads();

    float* sx = reinterpret_cast<float*>(sx4[warp]);
    float4* s4 = sx4[warp];

    for (int g = blockIdx.x; g < ngroups; g += gridDim.x) {
        const int rbase = g * RPG + warp * RPW;

        // prefetch first row into registers (coalesced float4)
        float4 r0, r1, r2, r3, r4;
        {
            int row = rbase;
            if (row < nrows) {
                const float4* p = reinterpret_cast<const float4*>(x + (size_t)row * OBS_DIM);
                r0 = p[lane]; r1 = p[lane + 32]; r2 = p[lane + 64]; r3 = p[lane + 96];
                if (lane < OBS_DIM / 4 - 128) r4 = p[lane + 128];
            }
        }

        #pragma unroll 1
        for (int j = 0; j < RPW; j++) {
            // ---- commit staged registers to shared ----
            s4[lane]       = r0;
            s4[lane + 32]  = r1;
            s4[lane + 64]  = r2;
            s4[lane + 96]  = r3;
            if (lane < OBS_DIM / 4 - 128) s4[lane + 128] = r4;
            __syncwarp();

            // ---- prefetch next row (overlaps all compute below) ----
            {
                int nrow = rbase + j + 1;
                if (j + 1 < RPW && nrow < nrows) {
                    const float4* p = reinterpret_cast<const float4*>(x + (size_t)nrow * OBS_DIM);
                    r0 = p[lane]; r1 = p[lane + 32]; r2 = p[lane + 64]; r3 = p[lane + 96];
                    if (lane < OBS_DIM / 4 - 128) r4 = p[lane + 128];
                }
            }

            // ---- logits: lane i handles slot i ----
            float logit = -1e30f;
            if (lane < OTHER_NUM) {
                const float* o = sx + SELF_DIM + lane * OTHER_DIM;
                float acc = 0.f;
                #pragma unroll
                for (int d = 0; d < OTHER_DIM; d += 4) {
                    float4 ov = *reinterpret_cast<const float4*>(o + d);
                    float4 wv = *reinterpret_cast<const float4*>(wsh + d);
                    acc += ov.x * wv.x + ov.y * wv.y + ov.z * wv.z + ov.w * wv.w;
                }
                logit = acc;
            }

            // ---- warp softmax over lanes 0..18 ----
            float mx = logit;
            #pragma unroll
            for (int off = 16; off > 0; off >>= 1)
                mx = fmaxf(mx, __shfl_xor_sync(0xffffffffu, mx, off));
            float e = (lane < OTHER_NUM) ? __expf(logit - mx) : 0.f;
            float sm = e;
            #pragma unroll
            for (int off = 16; off > 0; off >>= 1)
                sm += __shfl_xor_sync(0xffffffffu, sm, off);
            float att = e / sm;   // valid on lanes 0..18; 0 elsewhere

            // ---- pooling: lane d sums att_i * others[i][d] (att via shuffle) ----
            const int dl = (lane < OTHER_DIM) ? lane : 0;   // clamp, store predicated
            float p = 0.f;
            #pragma unroll
            for (int i = 0; i < OTHER_NUM; i++) {
                float a = __shfl_sync(0xffffffffu, att, i);
                p += a * sx[SELF_DIM + i * OTHER_DIM + dl];
            }
            if (lane < OTHER_DIM) pv[warp][j][SELF_DIM + lane] = p;
            pv[warp][j][lane] = sx[lane];                         // self[0..31]
            if (lane < SELF_DIM - 32) pv[warp][j][32 + lane] = sx[32 + lane];
            __syncwarp();   // pooling reads done before next iter's STS; pv visible
        }

        // ---- 8-row register-blocked GEMM: out = pv @ M' + c (f32x2 packed) ----
        // Lane l owns output features {2l, 2l+1}.
        u64 acc[RPW];
        {
            float2 ci = *reinterpret_cast<const float2*>(&csh[2 * lane]);
            u64 c0 = pk2(ci.x, ci.y);
            #pragma unroll
            for (int j = 0; j < RPW; j++) acc[j] = c0;
        }

        #pragma unroll
        for (int k0 = 0; k0 < 64; k0 += 4) {
            float qv[RPW][4];
            #pragma unroll
            for (int j = 0; j < RPW; j++) {
                float4 q = *reinterpret_cast<const float4*>(&pv[warp][j][k0]);
                qv[j][0] = q.x; qv[j][1] = q.y; qv[j][2] = q.z; qv[j][3] = q.w;
            }
            #pragma unroll
            for (int kk = 0; kk < 4; kk++) {
                u64 m = *reinterpret_cast<const u64*>(&Msh[(k0 + kk) * 64 + 2 * lane]);
                #pragma unroll
                for (int j = 0; j < RPW; j++) {
                    u64 pb = pk2(qv[j][kk], qv[j][kk]);
                    acc[j] = ffma2(pb, m, acc[j]);
                }
            }
        }

        #pragma unroll
        for (int j = 0; j < RPW; j++) {
            int row = rbase + j;
            if (row < nrows) {
                *reinterpret_cast<float2*>(out + (size_t)row * HID + 2 * lane) = upk2(acc[j]);
            }
        }
    }
}

// ---------------------------------------------------------------------------
extern "C" void kernel_launch(void* const* d_in, const int* in_sizes, int n_in,
                              void* d_out, int out_size) {
    const float* x  = (const float*)d_in[0];
    const float* Wa = (const float*)d_in[1];
    // d_in[2] = ba : softmax-invariant, unused
    const float* We = (const float*)d_in[3];
    const float* be = (const float*)d_in[4];
    const float* Ws = (const float*)d_in[5];
    const float* bs = (const float*)d_in[6];
    const float* Wo = (const float*)d_in[7];
    const float* bo = (const float*)d_in[8];
    float* out = (float*)d_out;

    const int nrows = in_sizes[0] / OBS_DIM;

    precompute_kernel<<<64, 64>>>(Wa, We, be, Ws, bs, Wo, bo);

    const int ngroups = (nrows + RPG - 1) / RPG;
    const int conc = 148 * 5;                          // est. concurrent blocks
    int waves = (ngroups + conc - 1) / conc;
    int grid  = (ngroups + waves - 1) / waves;         // balanced grid-stride
    gat_kernel<<<grid, NW * 32>>>(x, out, nrows, ngroups);
}

// round 10
// speedup vs baseline: 1.1878x; 1.0036x over previous
#include <cuda_runtime.h>
#include <math.h>

#define SELF_DIM  36
#define OTHER_DIM 28
#define OTHER_NUM 19
#define OBS_DIM   568        // 36 + 28*19
#define HID       64
#define NW        6          // warps per block
#define RPW       8          // rows per warp per GEMM group
#define RPG       (NW * RPW) // 48 rows per group

// Scratch (allocation-free). Aligned so we can read as float2/float4.
__device__ __align__(16) float g_M[64 * 64];
__device__ __align__(16) float g_c[64];
__device__ __align__(16) float g_w[OTHER_DIM];

// ---------------------------------------------------------------------------
// Fused-weight precompute:
//   M'[k][h] = (We @ Wo[:64])[k][h] + (k<36 ? ((Ws[:36]+Ws[36:]) @ Wo[64:])[k][h] : 0)
//   c[h]     = bo[h] + be @ Wo[:64] + bs @ Wo[64:]
//   w[d]     = Wa[36+d]    (self part of logits + ba are softmax-invariant)
// ---------------------------------------------------------------------------
__global__ void precompute_kernel(const float* __restrict__ Wa,
                                  const float* __restrict__ We,
                                  const float* __restrict__ be,
                                  const float* __restrict__ Ws,
                                  const float* __restrict__ bs,
                                  const float* __restrict__ Wo,
                                  const float* __restrict__ bo) {
    int k = blockIdx.x;   // 0..63
    int h = threadIdx.x;  // 0..63
    float acc = 0.f;
    #pragma unroll 8
    for (int j = 0; j < 64; j++)
        acc += We[k * HID + j] * Wo[j * HID + h];
    if (k < SELF_DIM) {
        #pragma unroll 8
        for (int j = 0; j < 64; j++)
            acc += (Ws[k * HID + j] + Ws[(k + SELF_DIM) * HID + j]) * Wo[(64 + j) * HID + h];
    }
    g_M[k * HID + h] = acc;

    if (k == 0) {
        float cc = bo[h];
        #pragma unroll 8
        for (int j = 0; j < 64; j++)
            cc += be[j] * Wo[j * HID + h] + bs[j] * Wo[(64 + j) * HID + h];
        g_c[h] = cc;
        if (h < OTHER_DIM) g_w[h] = Wa[SELF_DIM + h];
    }
}

// ---------------------------------------------------------------------------
// Packed fp32x2 helpers (Blackwell SIMD fp32; only reachable via PTX).
// ---------------------------------------------------------------------------
typedef unsigned long long u64;

__device__ __forceinline__ u64 pk2(float x, float y) {
    u64 u;
    asm("mov.b64 %0, {%1, %2};" : "=l"(u) : "f"(x), "f"(y));
    return u;
}
__device__ __forceinline__ float2 upk2(u64 u) {
    float2 f;
    asm("mov.b64 {%0, %1}, %2;" : "=f"(f.x), "=f"(f.y) : "l"(u));
    return f;
}
__device__ __forceinline__ u64 ffma2(u64 a, u64 b, u64 c) {
    u64 d;
    asm("fma.rn.f32x2 %0, %1, %2, %3;" : "=l"(d) : "l"(a), "l"(b), "l"(c));
    return d;
}

// ---------------------------------------------------------------------------
// Main kernel. Per row (one warp, 8 rows batched):
//   logits_i = others_i . w     (lane i, conflict-aware float4 smem reads)
//   att      = softmax          (warp shuffles)
//   pooled   = [self(36), sum_i att_i * others_i]   (lane d, conflict-free)
//   out      = pooled @ M' + c  (8-row register-blocked, f32x2-packed GEMM)
// Row staging is software-pipelined: next row's gmem loads issue while the
// current row computes, so DRAM latency is hidden inside the warp.
// ---------------------------------------------------------------------------
__global__ void __launch_bounds__(NW * 32)
gat_kernel(const float* __restrict__ x, float* __restrict__ out,
           int nrows, int ngroups) {
    __shared__ float4 sx4[NW][OBS_DIM / 4];          // 6 * 2272 B row staging
    __shared__ __align__(16) float Msh[64 * 64];     // 16 KB fused matrix
    __shared__ __align__(16) float pv[NW][RPW][64];  // pooled vectors, 12 KB
    __shared__ __align__(8)  float csh[64];
    __shared__ __align__(16) float wsh[OTHER_DIM];

    const int tid  = threadIdx.x;
    const int warp = tid >> 5;
    const int lane = tid & 31;

    for (int i = tid; i < 64 * 64; i += NW * 32) Msh[i] = g_M[i];
    if (tid < 64)                          csh[tid]      = g_c[tid];
    if (tid >= 64 && tid < 64 + OTHER_DIM) wsh[tid - 64] = g_w[tid - 64];
    __syncthreads();

    float* sx = reinterpret_cast<float*>(sx4[warp]);
    float4* s4 = sx4[warp];

    for (int g = blockIdx.x; g < ngroups; g += gridDim.x) {
        const int rbase = g * RPG + warp * RPW;

        // prefetch first row into registers (coalesced float4)
        float4 r0, r1, r2, r3, r4;
        {
            int row = rbase;
            if (row < nrows) {
                const float4* p = reinterpret_cast<const float4*>(x + (size_t)row * OBS_DIM);
                r0 = p[lane]; r1 = p[lane + 32]; r2 = p[lane + 64]; r3 = p[lane + 96];
                if (lane < OBS_DIM / 4 - 128) r4 = p[lane + 128];
            }
        }

        #pragma unroll 1
        for (int j = 0; j < RPW; j++) {
            // ---- commit staged registers to shared ----
            s4[lane]       = r0;
            s4[lane + 32]  = r1;
            s4[lane + 64]  = r2;
            s4[lane + 96]  = r3;
            if (lane < OBS_DIM / 4 - 128) s4[lane + 128] = r4;
            __syncwarp();

            // ---- prefetch next row (overlaps all compute below) ----
            {
                int nrow = rbase + j + 1;
                if (j + 1 < RPW && nrow < nrows) {
                    const float4* p = reinterpret_cast<const float4*>(x + (size_t)nrow * OBS_DIM);
                    r0 = p[lane]; r1 = p[lane + 32]; r2 = p[lane + 64]; r3 = p[lane + 96];
                    if (lane < OBS_DIM / 4 - 128) r4 = p[lane + 128];
                }
            }

            // ---- logits: lane i handles slot i ----
            float logit = -1e30f;
            if (lane < OTHER_NUM) {
                const float* o = sx + SELF_DIM + lane * OTHER_DIM;
                float acc = 0.f;
                #pragma unroll
                for (int d = 0; d < OTHER_DIM; d += 4) {
                    float4 ov = *reinterpret_cast<const float4*>(o + d);
                    float4 wv = *reinterpret_cast<const float4*>(wsh + d);
                    acc += ov.x * wv.x + ov.y * wv.y + ov.z * wv.z + ov.w * wv.w;
                }
                logit = acc;
            }

            // ---- warp softmax over lanes 0..18 ----
            float mx = logit;
            #pragma unroll
            for (int off = 16; off > 0; off >>= 1)
                mx = fmaxf(mx, __shfl_xor_sync(0xffffffffu, mx, off));
            float e = (lane < OTHER_NUM) ? __expf(logit - mx) : 0.f;
            float sm = e;
            #pragma unroll
            for (int off = 16; off > 0; off >>= 1)
                sm += __shfl_xor_sync(0xffffffffu, sm, off);
            float att = e / sm;   // valid on lanes 0..18; 0 elsewhere

            // ---- pooling: lane d sums att_i * others[i][d] (att via shuffle) ----
            const int dl = (lane < OTHER_DIM) ? lane : 0;   // clamp, store predicated
            float p = 0.f;
            #pragma unroll
            for (int i = 0; i < OTHER_NUM; i++) {
                float a = __shfl_sync(0xffffffffu, att, i);
                p += a * sx[SELF_DIM + i * OTHER_DIM + dl];
            }
            if (lane < OTHER_DIM) pv[warp][j][SELF_DIM + lane] = p;
            pv[warp][j][lane] = sx[lane];                         // self[0..31]
            if (lane < SELF_DIM - 32) pv[warp][j][32 + lane] = sx[32 + lane];
            __syncwarp();   // pooling reads done before next iter's STS; pv visible
        }

        // ---- 8-row register-blocked GEMM: out = pv @ M' + c (f32x2 packed) ----
        // Lane l owns output features {2l, 2l+1}.
        u64 acc[RPW];
        {
            float2 ci = *reinterpret_cast<const float2*>(&csh[2 * lane]);
            u64 c0 = pk2(ci.x, ci.y);
            #pragma unroll
            for (int j = 0; j < RPW; j++) acc[j] = c0;
        }

        #pragma unroll
        for (int k0 = 0; k0 < 64; k0 += 4) {
            float qv[RPW][4];
            #pragma unroll
            for (int j = 0; j < RPW; j++) {
                float4 q = *reinterpret_cast<const float4*>(&pv[warp][j][k0]);
                qv[j][0] = q.x; qv[j][1] = q.y; qv[j][2] = q.z; qv[j][3] = q.w;
            }
            #pragma unroll
            for (int kk = 0; kk < 4; kk++) {
                u64 m = *reinterpret_cast<const u64*>(&Msh[(k0 + kk) * 64 + 2 * lane]);
                #pragma unroll
                for (int j = 0; j < RPW; j++) {
                    u64 pb = pk2(qv[j][kk], qv[j][kk]);
                    acc[j] = ffma2(pb, m, acc[j]);
                }
            }
        }

        #pragma unroll
        for (int j = 0; j < RPW; j++) {
            int row = rbase + j;
            if (row < nrows) {
                *reinterpret_cast<float2*>(out + (size_t)row * HID + 2 * lane) = upk2(acc[j]);
            }
        }
    }
}

// ---------------------------------------------------------------------------
extern "C" void kernel_launch(void* const* d_in, const int* in_sizes, int n_in,
                              void* d_out, int out_size) {
    const float* x  = (const float*)d_in[0];
    const float* Wa = (const float*)d_in[1];
    // d_in[2] = ba : softmax-invariant, unused
    const float* We = (const float*)d_in[3];
    const float* be = (const float*)d_in[4];
    const float* Ws = (const float*)d_in[5];
    const float* bs = (const float*)d_in[6];
    const float* Wo = (const float*)d_in[7];
    const float* bo = (const float*)d_in[8];
    float* out = (float*)d_out;

    const int nrows = in_sizes[0] / OBS_DIM;

    precompute_kernel<<<64, 64>>>(Wa, We, be, Ws, bs, Wo, bo);

    const int ngroups = (nrows + RPG - 1) / RPG;
    const int conc = 148 * 5;                          // est. concurrent blocks
    int waves = (ngroups + conc - 1) / conc;
    int grid  = (ngroups + waves - 1) / waves;         // balanced grid-stride
    gat_kernel<<<grid, NW * 32>>>(x, out, nrows, ngroups);
}